// round 1
// baseline (speedup 1.0000x reference)
#include <cuda_runtime.h>
#include <math.h>

#define HID     2048
#define NHEADS  16
#define HDIM    128
#define BATCHSZ 2
#define SEQLEN  2048
#define MTOT    (BATCHSZ * SEQLEN)   // 4096

// Scratch (allocation-free): [b, h, s, d] layout for q/k/v, [m, hid] for attn out.
__device__ float g_q[BATCHSZ * NHEADS * SEQLEN * HDIM];
__device__ float g_k[BATCHSZ * NHEADS * SEQLEN * HDIM];
__device__ float g_v[BATCHSZ * NHEADS * SEQLEN * HDIM];
__device__ float g_attn[MTOT * HID];

// ---------------------------------------------------------------------------
// SGEMM body: C[M=4096, N=2048] = A[M,K=2048] @ W[N,K]^T + bias
// 128x128 block tile, 8x8 per thread, BK=16, 256 threads.
// MODE 0: Out[m*HID + n]            (plain row-major)
// MODE 1: Out[((b*NH+h)*SEQ+s)*HD+d] (split-head layout), m=b*SEQ+s, n=h*HD+d
// ---------------------------------------------------------------------------
template <int MODE>
__device__ __forceinline__ void gemm_body(const float* __restrict__ A,
                                          const float* __restrict__ W,
                                          const float* __restrict__ Bias,
                                          float* __restrict__ Out) {
    __shared__ float As[16][128];   // [k][m]
    __shared__ float Bs[16][128];   // [k][n]

    const int tid = threadIdx.x;
    const int tx  = tid & 15;       // n-dir
    const int ty  = tid >> 4;       // m-dir
    const int m0  = blockIdx.y * 128;
    const int n0  = blockIdx.x * 128;
    const int ldm = tid >> 2;         // 0..63
    const int ldk = (tid & 3) << 2;   // 0,4,8,12

    float acc[8][8];
#pragma unroll
    for (int i = 0; i < 8; i++)
#pragma unroll
        for (int j = 0; j < 8; j++) acc[i][j] = 0.f;

    const float* a0p = A + (size_t)(m0 + ldm)      * HID + ldk;
    const float* a1p = A + (size_t)(m0 + ldm + 64) * HID + ldk;
    const float* w0p = W + (size_t)(n0 + ldm)      * HID + ldk;
    const float* w1p = W + (size_t)(n0 + ldm + 64) * HID + ldk;

    for (int k0 = 0; k0 < HID; k0 += 16) {
        float4 ra0 = *(const float4*)(a0p + k0);
        float4 ra1 = *(const float4*)(a1p + k0);
        float4 rw0 = *(const float4*)(w0p + k0);
        float4 rw1 = *(const float4*)(w1p + k0);
        __syncthreads();   // previous tile's compute done before overwrite
        As[ldk + 0][ldm] = ra0.x; As[ldk + 1][ldm] = ra0.y;
        As[ldk + 2][ldm] = ra0.z; As[ldk + 3][ldm] = ra0.w;
        As[ldk + 0][ldm + 64] = ra1.x; As[ldk + 1][ldm + 64] = ra1.y;
        As[ldk + 2][ldm + 64] = ra1.z; As[ldk + 3][ldm + 64] = ra1.w;
        Bs[ldk + 0][ldm] = rw0.x; Bs[ldk + 1][ldm] = rw0.y;
        Bs[ldk + 2][ldm] = rw0.z; Bs[ldk + 3][ldm] = rw0.w;
        Bs[ldk + 0][ldm + 64] = rw1.x; Bs[ldk + 1][ldm + 64] = rw1.y;
        Bs[ldk + 2][ldm + 64] = rw1.z; Bs[ldk + 3][ldm + 64] = rw1.w;
        __syncthreads();

#pragma unroll
        for (int k = 0; k < 16; k++) {
            float4 xa = *(const float4*)&As[k][ty * 4];
            float4 xb = *(const float4*)&As[k][ty * 4 + 64];
            float4 yc = *(const float4*)&Bs[k][tx * 4];
            float4 yd = *(const float4*)&Bs[k][tx * 4 + 64];
            float av[8] = {xa.x, xa.y, xa.z, xa.w, xb.x, xb.y, xb.z, xb.w};
            float bv[8] = {yc.x, yc.y, yc.z, yc.w, yd.x, yd.y, yd.z, yd.w};
#pragma unroll
            for (int i = 0; i < 8; i++)
#pragma unroll
                for (int j = 0; j < 8; j++)
                    acc[i][j] = fmaf(av[i], bv[j], acc[i][j]);
        }
    }

    // Epilogue: bias + (optionally) split-head remap. Each (i, jh) group of 4
    // columns is contiguous and stays within a single head (tx*4+j < 64).
#pragma unroll
    for (int ih = 0; ih < 2; ih++) {
#pragma unroll
        for (int ii = 0; ii < 4; ii++) {
            const int i = ih * 4 + ii;
            const int m = m0 + ih * 64 + ty * 4 + ii;
#pragma unroll
            for (int jh = 0; jh < 2; jh++) {
                const int n = n0 + jh * 64 + tx * 4;
                float4 bb = *(const float4*)(Bias + n);
                float4 r;
                r.x = acc[i][jh * 4 + 0] + bb.x;
                r.y = acc[i][jh * 4 + 1] + bb.y;
                r.z = acc[i][jh * 4 + 2] + bb.z;
                r.w = acc[i][jh * 4 + 3] + bb.w;
                if (MODE == 0) {
                    *(float4*)(Out + (size_t)m * HID + n) = r;
                } else {
                    const int b = m >> 11;          // m / SEQLEN
                    const int s = m & (SEQLEN - 1);
                    const int h = n >> 7;           // n / HDIM
                    const int d = n & (HDIM - 1);
                    *(float4*)(Out + (((size_t)(b * NHEADS + h) * SEQLEN + s) * HDIM + d)) = r;
                }
            }
        }
    }
}

__global__ __launch_bounds__(256, 2)
void gemm_qkv_kernel(const float* __restrict__ x,
                     const float* __restrict__ wq, const float* __restrict__ wk,
                     const float* __restrict__ wv,
                     const float* __restrict__ bq, const float* __restrict__ bk,
                     const float* __restrict__ bv) {
    const int z = blockIdx.z;
    const float* W = (z == 0) ? wq : (z == 1 ? wk : wv);
    const float* B = (z == 0) ? bq : (z == 1 ? bk : bv);
    float* O       = (z == 0) ? g_q : (z == 1 ? g_k : g_v);
    gemm_body<1>(x, W, B, O);
}

__global__ __launch_bounds__(256, 2)
void gemm_out_kernel(const float* __restrict__ wo, const float* __restrict__ bo,
                     float* __restrict__ out) {
    gemm_body<0>(g_attn, wo, bo, out);
}

// ---------------------------------------------------------------------------
// Flash attention, fp32. One block = 64 q-rows of one (b,h); loop kv tiles of
// 64 with online softmax. 256 threads as 16(tx)x16(ty); scores 4x4/thread,
// O accumulator 4 rows x 8 d-cols/thread.
// Dynamic smem: Qs[128][64] + Ks[128][64] + Vs[64][128] + Ps[64][66]
// ---------------------------------------------------------------------------
#define ATTN_SMEM ((128 * 64 + 128 * 64 + 64 * 128 + 64 * 66) * 4)  // 115200 B

__global__ __launch_bounds__(256, 2)
void attn_kernel() {
    extern __shared__ float sm[];
    float* Qs = sm;                   // [d][m], d-major, prescaled
    float* Ks = sm + 128 * 64;        // [d][n]
    float* Vs = sm + 2 * 128 * 64;    // [n][d]
    float* Ps = sm + 3 * 128 * 64;    // [m][66]

    const int tid = threadIdx.x;
    const int tx  = tid & 15;
    const int ty  = tid >> 4;
    const int qt  = blockIdx.x;       // q tile 0..31
    const int bh  = blockIdx.y;       // b*16+h
    const int q0  = qt * 64;
    const float scale = 0.08838834764831845f;  // 1/sqrt(128)

    const float* Qp = g_q + (size_t)bh * SEQLEN * HDIM;
    const float* Kp = g_k + (size_t)bh * SEQLEN * HDIM;
    const float* Vp = g_v + (size_t)bh * SEQLEN * HDIM;

    // Load Q tile transposed + prescale by 1/sqrt(d)
    {
        const int r = tid >> 5;            // 0..7
        const int c = (tid & 31) << 2;     // 0..124
#pragma unroll
        for (int it = 0; it < 8; it++) {
            const int row = r + it * 8;
            float4 v = *(const float4*)(Qp + (size_t)(q0 + row) * HDIM + c);
            Qs[(c + 0) * 64 + row] = v.x * scale;
            Qs[(c + 1) * 64 + row] = v.y * scale;
            Qs[(c + 2) * 64 + row] = v.z * scale;
            Qs[(c + 3) * 64 + row] = v.w * scale;
        }
    }

    float mi[4], li[4], o[4][8];
#pragma unroll
    for (int i = 0; i < 4; i++) {
        mi[i] = -INFINITY;
        li[i] = 0.f;
#pragma unroll
        for (int c = 0; c < 8; c++) o[i][c] = 0.f;
    }

    for (int jt = 0; jt <= qt; jt++) {
        const int k0 = jt * 64;
        __syncthreads();  // Q store (1st iter) / previous PV reads done
        {
            const int r = tid >> 5;
            const int c = (tid & 31) << 2;
#pragma unroll
            for (int it = 0; it < 8; it++) {
                const int row = r + it * 8;
                float4 kv = *(const float4*)(Kp + (size_t)(k0 + row) * HDIM + c);
                Ks[(c + 0) * 64 + row] = kv.x;
                Ks[(c + 1) * 64 + row] = kv.y;
                Ks[(c + 2) * 64 + row] = kv.z;
                Ks[(c + 3) * 64 + row] = kv.w;
                float4 vv = *(const float4*)(Vp + (size_t)(k0 + row) * HDIM + c);
                *(float4*)&Vs[row * 128 + c] = vv;
            }
        }
        __syncthreads();

        // S = (Q*scale) @ K^T : 4x4 per thread over d=128
        float s[4][4];
#pragma unroll
        for (int i = 0; i < 4; i++)
#pragma unroll
            for (int j = 0; j < 4; j++) s[i][j] = 0.f;

#pragma unroll 4
        for (int d = 0; d < 128; d++) {
            float4 qa = *(const float4*)&Qs[d * 64 + ty * 4];
            float4 kb = *(const float4*)&Ks[d * 64 + tx * 4];
            float qv[4] = {qa.x, qa.y, qa.z, qa.w};
            float kv[4] = {kb.x, kb.y, kb.z, kb.w};
#pragma unroll
            for (int i = 0; i < 4; i++)
#pragma unroll
                for (int j = 0; j < 4; j++)
                    s[i][j] = fmaf(qv[i], kv[j], s[i][j]);
        }

        if (jt == qt) {  // diagonal tile: causal mask (k index > q index)
#pragma unroll
            for (int i = 0; i < 4; i++)
#pragma unroll
                for (int j = 0; j < 4; j++)
                    if (tx * 4 + j > ty * 4 + i) s[i][j] = -INFINITY;
        }

        // Online softmax. tx lives in low 4 lane bits -> xor-shuffle reduce.
#pragma unroll
        for (int i = 0; i < 4; i++) {
            float rmax = fmaxf(fmaxf(s[i][0], s[i][1]), fmaxf(s[i][2], s[i][3]));
#pragma unroll
            for (int off = 8; off >= 1; off >>= 1)
                rmax = fmaxf(rmax, __shfl_xor_sync(0xffffffffu, rmax, off));
            const float mnew = fmaxf(mi[i], rmax);
            const float corr = expf(mi[i] - mnew);  // mi=-inf on 1st tile -> 0
            float rsum = 0.f;
#pragma unroll
            for (int j = 0; j < 4; j++) {
                const float p = expf(s[i][j] - mnew);
                s[i][j] = p;
                rsum += p;
            }
#pragma unroll
            for (int off = 8; off >= 1; off >>= 1)
                rsum += __shfl_xor_sync(0xffffffffu, rsum, off);
            li[i] = li[i] * corr + rsum;
            mi[i] = mnew;
#pragma unroll
            for (int c = 0; c < 8; c++) o[i][c] *= corr;
#pragma unroll
            for (int j = 0; j < 4; j++)
                Ps[(ty * 4 + i) * 66 + tx * 4 + j] = s[i][j];
        }
        __syncthreads();

        // O += P @ V  (P: 64x64 in smem, V: 64x128 in smem)
#pragma unroll 2
        for (int k = 0; k < 64; k++) {
            const float p0 = Ps[(ty * 4 + 0) * 66 + k];
            const float p1 = Ps[(ty * 4 + 1) * 66 + k];
            const float p2 = Ps[(ty * 4 + 2) * 66 + k];
            const float p3 = Ps[(ty * 4 + 3) * 66 + k];
            float4 va = *(const float4*)&Vs[k * 128 + tx * 8];
            float4 vb = *(const float4*)&Vs[k * 128 + tx * 8 + 4];
            float vv[8] = {va.x, va.y, va.z, va.w, vb.x, vb.y, vb.z, vb.w};
#pragma unroll
            for (int c = 0; c < 8; c++) {
                o[0][c] = fmaf(p0, vv[c], o[0][c]);
                o[1][c] = fmaf(p1, vv[c], o[1][c]);
                o[2][c] = fmaf(p2, vv[c], o[2][c]);
                o[3][c] = fmaf(p3, vv[c], o[3][c]);
            }
        }
    }

    // Normalize and write attn output in [b, s, h*HD + d] layout
    const int b = bh >> 4, h = bh & 15;
#pragma unroll
    for (int i = 0; i < 4; i++) {
        const float inv = 1.0f / li[i];
        const size_t row = (size_t)b * SEQLEN + q0 + ty * 4 + i;
        const size_t col = (size_t)h * HDIM + tx * 8;
        float4 r0, r1;
        r0.x = o[i][0] * inv; r0.y = o[i][1] * inv;
        r0.z = o[i][2] * inv; r0.w = o[i][3] * inv;
        r1.x = o[i][4] * inv; r1.y = o[i][5] * inv;
        r1.z = o[i][6] * inv; r1.w = o[i][7] * inv;
        *(float4*)&g_attn[row * HID + col]     = r0;
        *(float4*)&g_attn[row * HID + col + 4] = r1;
    }
}

// ---------------------------------------------------------------------------
extern "C" void kernel_launch(void* const* d_in, const int* in_sizes, int n_in,
                              void* d_out, int out_size) {
    const float* x  = (const float*)d_in[0];
    const float* wq = (const float*)d_in[1];
    const float* wk = (const float*)d_in[2];
    const float* wv = (const float*)d_in[3];
    const float* wo = (const float*)d_in[4];
    const float* bq = (const float*)d_in[5];
    const float* bk = (const float*)d_in[6];
    const float* bv = (const float*)d_in[7];
    const float* bo = (const float*)d_in[8];
    float* out = (float*)d_out;

    cudaFuncSetAttribute(attn_kernel,
                         cudaFuncAttributeMaxDynamicSharedMemorySize, ATTN_SMEM);

    // 1) QKV projections (fused launch; z selects weight set)
    gemm_qkv_kernel<<<dim3(HID / 128, MTOT / 128, 3), 256>>>(x, wq, wk, wv, bq, bk, bv);
    // 2) Causal flash attention
    attn_kernel<<<dim3(SEQLEN / 64, BATCHSZ * NHEADS), 256, ATTN_SMEM>>>();
    // 3) Output projection
    gemm_out_kernel<<<dim3(HID / 128, MTOT / 128), 256>>>(wo, bo, out);
}

// round 4
// speedup vs baseline: 1.4962x; 1.4962x over previous
#include <cuda_runtime.h>
#include <cuda_bf16.h>
#include <math.h>
#include <cstdint>

#define HID     2048
#define NHEADS  16
#define HDIM    128
#define BATCHSZ 2
#define SEQLEN  2048
#define MTOT    (BATCHSZ * SEQLEN)   // 4096

// Scratch (allocation-free)
__device__ float g_q[BATCHSZ * NHEADS * SEQLEN * HDIM];
__device__ float g_k[BATCHSZ * NHEADS * SEQLEN * HDIM];
__device__ float g_v[BATCHSZ * NHEADS * SEQLEN * HDIM];
__device__ float g_attn[MTOT * HID];

// ============================ helpers ======================================
__device__ __forceinline__ uint32_t smem_u32(const void* p) {
    uint32_t a;
    asm("{ .reg .u64 t; cvta.to.shared.u64 t, %1; cvt.u32.u64 %0, t; }"
        : "=r"(a) : "l"(p));
    return a;
}

#define LDSM_X4(r0, r1, r2, r3, addr)                                    \
    asm volatile("ldmatrix.sync.aligned.m8n8.x4.shared.b16 "             \
                 "{%0,%1,%2,%3}, [%4];"                                  \
                 : "=r"(r0), "=r"(r1), "=r"(r2), "=r"(r3) : "r"(addr))

#define MMA_BF16(c0, c1, c2, c3, a0, a1, a2, a3, b0, b1)                 \
    asm volatile("mma.sync.aligned.m16n8k16.row.col.f32.bf16.bf16.f32 "  \
                 "{%0,%1,%2,%3}, {%4,%5,%6,%7}, {%8,%9}, {%0,%1,%2,%3};" \
                 : "+f"(c0), "+f"(c1), "+f"(c2), "+f"(c3)                \
                 : "r"(a0), "r"(a1), "r"(a2), "r"(a3), "r"(b0), "r"(b1))

__device__ __forceinline__ void split_bf16(float x, __nv_bfloat16& hi, __nv_bfloat16& lo) {
    hi = __float2bfloat16_rn(x);
    lo = __float2bfloat16_rn(x - __bfloat162float(hi));
}

// ====================== mma.sync bf16-split GEMM ===========================
// C[M=4096, N=2048] = A[M,K=2048] @ W[N,K]^T + bias
// CTA 128x128, 256 threads = 8 warps (2 in M x 4 in N), warp tile 64x32.
// K chunk = 32 floats. Smem: Ahi/Alo/Whi/Wlo as [128][40] bf16 (pad -> no
// ldmatrix bank conflicts). 3 mma terms: hi*hi + hi*lo + lo*hi, fp32 accum.
#define KSTRIDE 40                       // bf16 elems per smem row (pad 32->40)
#define TILE_B  (128 * KSTRIDE * 2)      // 10240 B per tile
#define GSM_TOTAL (4 * TILE_B)           // 40960 B

// MODE 0: Out[m*HID + n]; MODE 1: split-head [b,h,s,d]
template <int MODE>
__device__ __forceinline__ void gemm_mma_body(const float* __restrict__ A,
                                              const float* __restrict__ W,
                                              const float* __restrict__ Bias,
                                              float* __restrict__ Out) {
    extern __shared__ char sm[];
    const uint32_t smem_base = smem_u32(sm);
    const int tid  = threadIdx.x;
    const int wid  = tid >> 5;
    const int lane = tid & 31;
    const int m0 = blockIdx.y * 128;
    const int n0 = blockIdx.x * 128;
    const int wm = wid & 1;              // 0..1
    const int wn = wid >> 1;             // 0..3

    // loader mapping: 128 rows x 8 float4-cols, 4 rows per thread
    const int frow = tid >> 3;           // 0..31
    const int fcol = (tid & 7) * 4;      // 0,4,...,28

    // ldmatrix lane addressing (same generator for A and B tiles)
    const int lrow = (lane & 7) + ((lane >> 3) & 1) * 8;
    const int lk   = (lane >> 4) * 8;

    const uint32_t a_hi_base = smem_base + (uint32_t)(((wm * 64 + lrow) * KSTRIDE + lk) * 2);
    const uint32_t b_hi_base = smem_base + 2 * TILE_B +
                               (uint32_t)(((wn * 32 + lrow) * KSTRIDE + lk) * 2);

    __nv_bfloat162* sAhi = (__nv_bfloat162*)(sm);
    __nv_bfloat162* sAlo = (__nv_bfloat162*)(sm + TILE_B);
    __nv_bfloat162* sWhi = (__nv_bfloat162*)(sm + 2 * TILE_B);
    __nv_bfloat162* sWlo = (__nv_bfloat162*)(sm + 3 * TILE_B);

    float acc[4][4][4];
#pragma unroll
    for (int i = 0; i < 4; i++)
#pragma unroll
        for (int j = 0; j < 4; j++)
#pragma unroll
            for (int c = 0; c < 4; c++) acc[i][j][c] = 0.f;

    const float* Ap = A + (size_t)(m0 + frow) * HID + fcol;
    const float* Wp = W + (size_t)(n0 + frow) * HID + fcol;

    float4 ra[4], rw[4];
#pragma unroll
    for (int i = 0; i < 4; i++) {
        ra[i] = *(const float4*)(Ap + (size_t)i * 32 * HID);
        rw[i] = *(const float4*)(Wp + (size_t)i * 32 * HID);
    }

    for (int kc = 0; kc < HID / 32; kc++) {
        __syncthreads();   // previous chunk's mma reads done before overwrite
#pragma unroll
        for (int i = 0; i < 4; i++) {
            const int row = frow + i * 32;
            const int idx = (row * KSTRIDE + fcol) >> 1;   // bfloat162 units
            __nv_bfloat16 hx, lx, hy, ly;
            split_bf16(ra[i].x, hx, lx); split_bf16(ra[i].y, hy, ly);
            sAhi[idx]     = __nv_bfloat162(hx, hy);
            sAlo[idx]     = __nv_bfloat162(lx, ly);
            split_bf16(ra[i].z, hx, lx); split_bf16(ra[i].w, hy, ly);
            sAhi[idx + 1] = __nv_bfloat162(hx, hy);
            sAlo[idx + 1] = __nv_bfloat162(lx, ly);
            split_bf16(rw[i].x, hx, lx); split_bf16(rw[i].y, hy, ly);
            sWhi[idx]     = __nv_bfloat162(hx, hy);
            sWlo[idx]     = __nv_bfloat162(lx, ly);
            split_bf16(rw[i].z, hx, lx); split_bf16(rw[i].w, hy, ly);
            sWhi[idx + 1] = __nv_bfloat162(hx, hy);
            sWlo[idx + 1] = __nv_bfloat162(lx, ly);
        }
        __syncthreads();

        if (kc + 1 < HID / 32) {   // prefetch next chunk (hidden behind mma)
            const int koff = (kc + 1) * 32;
#pragma unroll
            for (int i = 0; i < 4; i++) {
                ra[i] = *(const float4*)(Ap + (size_t)i * 32 * HID + koff);
                rw[i] = *(const float4*)(Wp + (size_t)i * 32 * HID + koff);
            }
        }

#pragma unroll
        for (int ks = 0; ks < 2; ks++) {
            const uint32_t koffb = (uint32_t)(ks * 16 * 2);
            // B fragments: pair p covers nf=2p (regs r0,r2) and nf=2p+1 (r1,r3)
            uint32_t bh[4][2], bl[4][2];
#pragma unroll
            for (int p = 0; p < 2; p++) {
                const uint32_t ba = b_hi_base + (uint32_t)(p * 16 * KSTRIDE * 2) + koffb;
                uint32_t r0, r1, r2, r3;
                LDSM_X4(r0, r1, r2, r3, ba);
                bh[2 * p][0] = r0; bh[2 * p][1] = r2;
                bh[2 * p + 1][0] = r1; bh[2 * p + 1][1] = r3;
                LDSM_X4(r0, r1, r2, r3, ba + TILE_B);
                bl[2 * p][0] = r0; bl[2 * p][1] = r2;
                bl[2 * p + 1][0] = r1; bl[2 * p + 1][1] = r3;
            }
#pragma unroll
            for (int mf = 0; mf < 4; mf++) {
                const uint32_t aa = a_hi_base + (uint32_t)(mf * 16 * KSTRIDE * 2) + koffb;
                uint32_t ah0, ah1, ah2, ah3, al0, al1, al2, al3;
                LDSM_X4(ah0, ah1, ah2, ah3, aa);
                LDSM_X4(al0, al1, al2, al3, aa + TILE_B);
#pragma unroll
                for (int nf = 0; nf < 4; nf++) {
                    MMA_BF16(acc[mf][nf][0], acc[mf][nf][1], acc[mf][nf][2], acc[mf][nf][3],
                             ah0, ah1, ah2, ah3, bh[nf][0], bh[nf][1]);
                    MMA_BF16(acc[mf][nf][0], acc[mf][nf][1], acc[mf][nf][2], acc[mf][nf][3],
                             ah0, ah1, ah2, ah3, bl[nf][0], bl[nf][1]);
                    MMA_BF16(acc[mf][nf][0], acc[mf][nf][1], acc[mf][nf][2], acc[mf][nf][3],
                             al0, al1, al2, al3, bh[nf][0], bh[nf][1]);
                }
            }
        }
    }

    // Epilogue: c0,c1 -> (row g, col 2t..2t+1); c2,c3 -> row g+8
    const int g = lane >> 2;
    const int t = lane & 3;
#pragma unroll
    for (int mf = 0; mf < 4; mf++) {
#pragma unroll
        for (int nf = 0; nf < 4; nf++) {
            const int m_lo = m0 + wm * 64 + mf * 16 + g;
            const int n    = n0 + wn * 32 + nf * 8 + t * 2;
            const float2 bb = *(const float2*)(Bias + n);
            float2 r0, r1;
            r0.x = acc[mf][nf][0] + bb.x; r0.y = acc[mf][nf][1] + bb.y;
            r1.x = acc[mf][nf][2] + bb.x; r1.y = acc[mf][nf][3] + bb.y;
            if (MODE == 0) {
                *(float2*)(Out + (size_t)m_lo * HID + n)       = r0;
                *(float2*)(Out + (size_t)(m_lo + 8) * HID + n) = r1;
            } else {
                const int h = n >> 7;
                const int d = n & (HDIM - 1);
                const int b0b = m_lo >> 11, s0 = m_lo & (SEQLEN - 1);
                const int b1b = (m_lo + 8) >> 11, s1 = (m_lo + 8) & (SEQLEN - 1);
                *(float2*)(Out + (((size_t)(b0b * NHEADS + h) * SEQLEN + s0) * HDIM + d)) = r0;
                *(float2*)(Out + (((size_t)(b1b * NHEADS + h) * SEQLEN + s1) * HDIM + d)) = r1;
            }
        }
    }
}

__global__ __launch_bounds__(256)
void gemm_qkv_kernel(const float* __restrict__ x,
                     const float* __restrict__ wq, const float* __restrict__ wk,
                     const float* __restrict__ wv,
                     const float* __restrict__ bq, const float* __restrict__ bk,
                     const float* __restrict__ bv) {
    const int z = blockIdx.z;
    const float* W = (z == 0) ? wq : (z == 1 ? wk : wv);
    const float* B = (z == 0) ? bq : (z == 1 ? bk : bv);
    float* O       = (z == 0) ? g_q : (z == 1 ? g_k : g_v);
    gemm_mma_body<1>(x, W, B, O);
}

__global__ __launch_bounds__(256)
void gemm_out_kernel(const float* __restrict__ wo, const float* __restrict__ bo,
                     float* __restrict__ out) {
    gemm_mma_body<0>(g_attn, wo, bo, out);
}

// ---------------------------------------------------------------------------
// Flash attention, fp32 (unchanged from R1 passing version)
// ---------------------------------------------------------------------------
#define ATTN_SMEM ((128 * 64 + 128 * 64 + 64 * 128 + 64 * 66) * 4)  // 115200 B

__global__ __launch_bounds__(256, 2)
void attn_kernel() {
    extern __shared__ float smf[];
    float* Qs = smf;                   // [d][m], prescaled
    float* Ks = smf + 128 * 64;        // [d][n]
    float* Vs = smf + 2 * 128 * 64;    // [n][d]
    float* Ps = smf + 3 * 128 * 64;    // [m][66]

    const int tid = threadIdx.x;
    const int tx  = tid & 15;
    const int ty  = tid >> 4;
    const int qt  = blockIdx.x;
    const int bh  = blockIdx.y;
    const int q0  = qt * 64;
    const float scale = 0.08838834764831845f;

    const float* Qp = g_q + (size_t)bh * SEQLEN * HDIM;
    const float* Kp = g_k + (size_t)bh * SEQLEN * HDIM;
    const float* Vp = g_v + (size_t)bh * SEQLEN * HDIM;

    {
        const int r = tid >> 5;
        const int c = (tid & 31) << 2;
#pragma unroll
        for (int it = 0; it < 8; it++) {
            const int row = r + it * 8;
            float4 v = *(const float4*)(Qp + (size_t)(q0 + row) * HDIM + c);
            Qs[(c + 0) * 64 + row] = v.x * scale;
            Qs[(c + 1) * 64 + row] = v.y * scale;
            Qs[(c + 2) * 64 + row] = v.z * scale;
            Qs[(c + 3) * 64 + row] = v.w * scale;
        }
    }

    float mi[4], li[4], o[4][8];
#pragma unroll
    for (int i = 0; i < 4; i++) {
        mi[i] = -INFINITY;
        li[i] = 0.f;
#pragma unroll
        for (int c = 0; c < 8; c++) o[i][c] = 0.f;
    }

    for (int jt = 0; jt <= qt; jt++) {
        const int k0 = jt * 64;
        __syncthreads();
        {
            const int r = tid >> 5;
            const int c = (tid & 31) << 2;
#pragma unroll
            for (int it = 0; it < 8; it++) {
                const int row = r + it * 8;
                float4 kv = *(const float4*)(Kp + (size_t)(k0 + row) * HDIM + c);
                Ks[(c + 0) * 64 + row] = kv.x;
                Ks[(c + 1) * 64 + row] = kv.y;
                Ks[(c + 2) * 64 + row] = kv.z;
                Ks[(c + 3) * 64 + row] = kv.w;
                float4 vv = *(const float4*)(Vp + (size_t)(k0 + row) * HDIM + c);
                *(float4*)&Vs[row * 128 + c] = vv;
            }
        }
        __syncthreads();

        float s[4][4];
#pragma unroll
        for (int i = 0; i < 4; i++)
#pragma unroll
            for (int j = 0; j < 4; j++) s[i][j] = 0.f;

#pragma unroll 4
        for (int d = 0; d < 128; d++) {
            float4 qa = *(const float4*)&Qs[d * 64 + ty * 4];
            float4 kb = *(const float4*)&Ks[d * 64 + tx * 4];
            float qv[4] = {qa.x, qa.y, qa.z, qa.w};
            float kv[4] = {kb.x, kb.y, kb.z, kb.w};
#pragma unroll
            for (int i = 0; i < 4; i++)
#pragma unroll
                for (int j = 0; j < 4; j++)
                    s[i][j] = fmaf(qv[i], kv[j], s[i][j]);
        }

        if (jt == qt) {
#pragma unroll
            for (int i = 0; i < 4; i++)
#pragma unroll
                for (int j = 0; j < 4; j++)
                    if (tx * 4 + j > ty * 4 + i) s[i][j] = -INFINITY;
        }

#pragma unroll
        for (int i = 0; i < 4; i++) {
            float rmax = fmaxf(fmaxf(s[i][0], s[i][1]), fmaxf(s[i][2], s[i][3]));
#pragma unroll
            for (int off = 8; off >= 1; off >>= 1)
                rmax = fmaxf(rmax, __shfl_xor_sync(0xffffffffu, rmax, off));
            const float mnew = fmaxf(mi[i], rmax);
            const float corr = expf(mi[i] - mnew);
            float rsum = 0.f;
#pragma unroll
            for (int j = 0; j < 4; j++) {
                const float p = expf(s[i][j] - mnew);
                s[i][j] = p;
                rsum += p;
            }
#pragma unroll
            for (int off = 8; off >= 1; off >>= 1)
                rsum += __shfl_xor_sync(0xffffffffu, rsum, off);
            li[i] = li[i] * corr + rsum;
            mi[i] = mnew;
#pragma unroll
            for (int c = 0; c < 8; c++) o[i][c] *= corr;
#pragma unroll
            for (int j = 0; j < 4; j++)
                Ps[(ty * 4 + i) * 66 + tx * 4 + j] = s[i][j];
        }
        __syncthreads();

#pragma unroll 2
        for (int k = 0; k < 64; k++) {
            const float p0 = Ps[(ty * 4 + 0) * 66 + k];
            const float p1 = Ps[(ty * 4 + 1) * 66 + k];
            const float p2 = Ps[(ty * 4 + 2) * 66 + k];
            const float p3 = Ps[(ty * 4 + 3) * 66 + k];
            float4 va = *(const float4*)&Vs[k * 128 + tx * 8];
            float4 vb = *(const float4*)&Vs[k * 128 + tx * 8 + 4];
            float vv[8] = {va.x, va.y, va.z, va.w, vb.x, vb.y, vb.z, vb.w};
#pragma unroll
            for (int c = 0; c < 8; c++) {
                o[0][c] = fmaf(p0, vv[c], o[0][c]);
                o[1][c] = fmaf(p1, vv[c], o[1][c]);
                o[2][c] = fmaf(p2, vv[c], o[2][c]);
                o[3][c] = fmaf(p3, vv[c], o[3][c]);
            }
        }
    }

    const int b = bh >> 4, h = bh & 15;
#pragma unroll
    for (int i = 0; i < 4; i++) {
        const float inv = 1.0f / li[i];
        const size_t row = (size_t)b * SEQLEN + q0 + ty * 4 + i;
        const size_t col = (size_t)h * HDIM + tx * 8;
        float4 r0, r1;
        r0.x = o[i][0] * inv; r0.y = o[i][1] * inv;
        r0.z = o[i][2] * inv; r0.w = o[i][3] * inv;
        r1.x = o[i][4] * inv; r1.y = o[i][5] * inv;
        r1.z = o[i][6] * inv; r1.w = o[i][7] * inv;
        *(float4*)&g_attn[row * HID + col]     = r0;
        *(float4*)&g_attn[row * HID + col + 4] = r1;
    }
}

// ---------------------------------------------------------------------------
extern "C" void kernel_launch(void* const* d_in, const int* in_sizes, int n_in,
                              void* d_out, int out_size) {
    const float* x  = (const float*)d_in[0];
    const float* wq = (const float*)d_in[1];
    const float* wk = (const float*)d_in[2];
    const float* wv = (const float*)d_in[3];
    const float* wo = (const float*)d_in[4];
    const float* bq = (const float*)d_in[5];
    const float* bk = (const float*)d_in[6];
    const float* bv = (const float*)d_in[7];
    const float* bo = (const float*)d_in[8];
    float* out = (float*)d_out;

    cudaFuncSetAttribute(gemm_qkv_kernel,
                         cudaFuncAttributeMaxDynamicSharedMemorySize, GSM_TOTAL);
    cudaFuncSetAttribute(gemm_out_kernel,
                         cudaFuncAttributeMaxDynamicSharedMemorySize, GSM_TOTAL);
    cudaFuncSetAttribute(attn_kernel,
                         cudaFuncAttributeMaxDynamicSharedMemorySize, ATTN_SMEM);

    // 1) QKV projections on mma.sync bf16 (3-term split)
    gemm_qkv_kernel<<<dim3(HID / 128, MTOT / 128, 3), 256, GSM_TOTAL>>>(
        x, wq, wk, wv, bq, bk, bv);
    // 2) Causal flash attention (fp32)
    attn_kernel<<<dim3(SEQLEN / 64, BATCHSZ * NHEADS), 256, ATTN_SMEM>>>();
    // 3) Output projection on mma.sync bf16
    gemm_out_kernel<<<dim3(HID / 128, MTOT / 128), 256, GSM_TOTAL>>>(wo, bo, out);
}

// round 5
// speedup vs baseline: 2.3013x; 1.5381x over previous
#include <cuda_runtime.h>
#include <cuda_bf16.h>
#include <math.h>
#include <cstdint>

#define HID     2048
#define NHEADS  16
#define HDIM    128
#define BATCHSZ 2
#define SEQLEN  2048
#define MTOT    (BATCHSZ * SEQLEN)   // 4096

// Scratch (allocation-free)
__device__ float g_q[BATCHSZ * NHEADS * SEQLEN * HDIM];
__device__ float g_k[BATCHSZ * NHEADS * SEQLEN * HDIM];
__device__ float g_v[BATCHSZ * NHEADS * SEQLEN * HDIM];
__device__ float g_attn[MTOT * HID];

// ============================ helpers ======================================
__device__ __forceinline__ uint32_t smem_u32(const void* p) {
    uint32_t a;
    asm("{ .reg .u64 t; cvta.to.shared.u64 t, %1; cvt.u32.u64 %0, t; }"
        : "=r"(a) : "l"(p));
    return a;
}

#define LDSM_X4(r0, r1, r2, r3, addr)                                    \
    asm volatile("ldmatrix.sync.aligned.m8n8.x4.shared.b16 "             \
                 "{%0,%1,%2,%3}, [%4];"                                  \
                 : "=r"(r0), "=r"(r1), "=r"(r2), "=r"(r3) : "r"(addr))

#define MMA_BF16(c0, c1, c2, c3, a0, a1, a2, a3, b0, b1)                 \
    asm volatile("mma.sync.aligned.m16n8k16.row.col.f32.bf16.bf16.f32 "  \
                 "{%0,%1,%2,%3}, {%4,%5,%6,%7}, {%8,%9}, {%0,%1,%2,%3};" \
                 : "+f"(c0), "+f"(c1), "+f"(c2), "+f"(c3)                \
                 : "r"(a0), "r"(a1), "r"(a2), "r"(a3), "r"(b0), "r"(b1))

__device__ __forceinline__ void split_bf16(float x, __nv_bfloat16& hi, __nv_bfloat16& lo) {
    hi = __float2bfloat16_rn(x);
    lo = __float2bfloat16_rn(x - __bfloat162float(hi));
}

// ====================== mma.sync bf16-split GEMM ===========================
// (unchanged from R4 passing version)
#define KSTRIDE 40
#define TILE_B  (128 * KSTRIDE * 2)
#define GSM_TOTAL (4 * TILE_B)

template <int MODE>
__device__ __forceinline__ void gemm_mma_body(const float* __restrict__ A,
                                              const float* __restrict__ W,
                                              const float* __restrict__ Bias,
                                              float* __restrict__ Out) {
    extern __shared__ char sm[];
    const uint32_t smem_base = smem_u32(sm);
    const int tid  = threadIdx.x;
    const int wid  = tid >> 5;
    const int lane = tid & 31;
    const int m0 = blockIdx.y * 128;
    const int n0 = blockIdx.x * 128;
    const int wm = wid & 1;
    const int wn = wid >> 1;

    const int frow = tid >> 3;
    const int fcol = (tid & 7) * 4;

    const int lrow = (lane & 7) + ((lane >> 3) & 1) * 8;
    const int lk   = (lane >> 4) * 8;

    const uint32_t a_hi_base = smem_base + (uint32_t)(((wm * 64 + lrow) * KSTRIDE + lk) * 2);
    const uint32_t b_hi_base = smem_base + 2 * TILE_B +
                               (uint32_t)(((wn * 32 + lrow) * KSTRIDE + lk) * 2);

    __nv_bfloat162* sAhi = (__nv_bfloat162*)(sm);
    __nv_bfloat162* sAlo = (__nv_bfloat162*)(sm + TILE_B);
    __nv_bfloat162* sWhi = (__nv_bfloat162*)(sm + 2 * TILE_B);
    __nv_bfloat162* sWlo = (__nv_bfloat162*)(sm + 3 * TILE_B);

    float acc[4][4][4];
#pragma unroll
    for (int i = 0; i < 4; i++)
#pragma unroll
        for (int j = 0; j < 4; j++)
#pragma unroll
            for (int c = 0; c < 4; c++) acc[i][j][c] = 0.f;

    const float* Ap = A + (size_t)(m0 + frow) * HID + fcol;
    const float* Wp = W + (size_t)(n0 + frow) * HID + fcol;

    float4 ra[4], rw[4];
#pragma unroll
    for (int i = 0; i < 4; i++) {
        ra[i] = *(const float4*)(Ap + (size_t)i * 32 * HID);
        rw[i] = *(const float4*)(Wp + (size_t)i * 32 * HID);
    }

    for (int kc = 0; kc < HID / 32; kc++) {
        __syncthreads();
#pragma unroll
        for (int i = 0; i < 4; i++) {
            const int row = frow + i * 32;
            const int idx = (row * KSTRIDE + fcol) >> 1;
            __nv_bfloat16 hx, lx, hy, ly;
            split_bf16(ra[i].x, hx, lx); split_bf16(ra[i].y, hy, ly);
            sAhi[idx]     = __nv_bfloat162(hx, hy);
            sAlo[idx]     = __nv_bfloat162(lx, ly);
            split_bf16(ra[i].z, hx, lx); split_bf16(ra[i].w, hy, ly);
            sAhi[idx + 1] = __nv_bfloat162(hx, hy);
            sAlo[idx + 1] = __nv_bfloat162(lx, ly);
            split_bf16(rw[i].x, hx, lx); split_bf16(rw[i].y, hy, ly);
            sWhi[idx]     = __nv_bfloat162(hx, hy);
            sWlo[idx]     = __nv_bfloat162(lx, ly);
            split_bf16(rw[i].z, hx, lx); split_bf16(rw[i].w, hy, ly);
            sWhi[idx + 1] = __nv_bfloat162(hx, hy);
            sWlo[idx + 1] = __nv_bfloat162(lx, ly);
        }
        __syncthreads();

        if (kc + 1 < HID / 32) {
            const int koff = (kc + 1) * 32;
#pragma unroll
            for (int i = 0; i < 4; i++) {
                ra[i] = *(const float4*)(Ap + (size_t)i * 32 * HID + koff);
                rw[i] = *(const float4*)(Wp + (size_t)i * 32 * HID + koff);
            }
        }

#pragma unroll
        for (int ks = 0; ks < 2; ks++) {
            const uint32_t koffb = (uint32_t)(ks * 16 * 2);
            uint32_t bh[4][2], bl[4][2];
#pragma unroll
            for (int p = 0; p < 2; p++) {
                const uint32_t ba = b_hi_base + (uint32_t)(p * 16 * KSTRIDE * 2) + koffb;
                uint32_t r0, r1, r2, r3;
                LDSM_X4(r0, r1, r2, r3, ba);
                bh[2 * p][0] = r0; bh[2 * p][1] = r2;
                bh[2 * p + 1][0] = r1; bh[2 * p + 1][1] = r3;
                LDSM_X4(r0, r1, r2, r3, ba + TILE_B);
                bl[2 * p][0] = r0; bl[2 * p][1] = r2;
                bl[2 * p + 1][0] = r1; bl[2 * p + 1][1] = r3;
            }
#pragma unroll
            for (int mf = 0; mf < 4; mf++) {
                const uint32_t aa = a_hi_base + (uint32_t)(mf * 16 * KSTRIDE * 2) + koffb;
                uint32_t ah0, ah1, ah2, ah3, al0, al1, al2, al3;
                LDSM_X4(ah0, ah1, ah2, ah3, aa);
                LDSM_X4(al0, al1, al2, al3, aa + TILE_B);
#pragma unroll
                for (int nf = 0; nf < 4; nf++) {
                    MMA_BF16(acc[mf][nf][0], acc[mf][nf][1], acc[mf][nf][2], acc[mf][nf][3],
                             ah0, ah1, ah2, ah3, bh[nf][0], bh[nf][1]);
                    MMA_BF16(acc[mf][nf][0], acc[mf][nf][1], acc[mf][nf][2], acc[mf][nf][3],
                             ah0, ah1, ah2, ah3, bl[nf][0], bl[nf][1]);
                    MMA_BF16(acc[mf][nf][0], acc[mf][nf][1], acc[mf][nf][2], acc[mf][nf][3],
                             al0, al1, al2, al3, bh[nf][0], bh[nf][1]);
                }
            }
        }
    }

    const int g = lane >> 2;
    const int t = lane & 3;
#pragma unroll
    for (int mf = 0; mf < 4; mf++) {
#pragma unroll
        for (int nf = 0; nf < 4; nf++) {
            const int m_lo = m0 + wm * 64 + mf * 16 + g;
            const int n    = n0 + wn * 32 + nf * 8 + t * 2;
            const float2 bb = *(const float2*)(Bias + n);
            float2 r0, r1;
            r0.x = acc[mf][nf][0] + bb.x; r0.y = acc[mf][nf][1] + bb.y;
            r1.x = acc[mf][nf][2] + bb.x; r1.y = acc[mf][nf][3] + bb.y;
            if (MODE == 0) {
                *(float2*)(Out + (size_t)m_lo * HID + n)       = r0;
                *(float2*)(Out + (size_t)(m_lo + 8) * HID + n) = r1;
            } else {
                const int h = n >> 7;
                const int d = n & (HDIM - 1);
                const int b0b = m_lo >> 11, s0 = m_lo & (SEQLEN - 1);
                const int b1b = (m_lo + 8) >> 11, s1 = (m_lo + 8) & (SEQLEN - 1);
                *(float2*)(Out + (((size_t)(b0b * NHEADS + h) * SEQLEN + s0) * HDIM + d)) = r0;
                *(float2*)(Out + (((size_t)(b1b * NHEADS + h) * SEQLEN + s1) * HDIM + d)) = r1;
            }
        }
    }
}

__global__ __launch_bounds__(256)
void gemm_qkv_kernel(const float* __restrict__ x,
                     const float* __restrict__ wq, const float* __restrict__ wk,
                     const float* __restrict__ wv,
                     const float* __restrict__ bq, const float* __restrict__ bk,
                     const float* __restrict__ bv) {
    const int z = blockIdx.z;
    const float* W = (z == 0) ? wq : (z == 1 ? wk : wv);
    const float* B = (z == 0) ? bq : (z == 1 ? bk : bv);
    float* O       = (z == 0) ? g_q : (z == 1 ? g_k : g_v);
    gemm_mma_body<1>(x, W, B, O);
}

__global__ __launch_bounds__(256)
void gemm_out_kernel(const float* __restrict__ wo, const float* __restrict__ bo,
                     float* __restrict__ out) {
    gemm_mma_body<0>(g_attn, wo, bo, out);
}

// ===================== Flash attention on mma.sync bf16 ====================
// CTA = 128 q-rows of one (b,h). 8 warps; warp w owns q-rows [w*16, w*16+16).
// kv tile = 64. Split bf16 (hi+lo, 3 terms) for both QK^T and PV.
// Smem: Qhi/Qlo [128][136], Khi/Klo [64][136], Vhi/Vlo (transposed) [128][72],
//       Phi/Plo [128][72]. Total 178176 B -> 1 CTA/SM.
#define AT_QS 136
#define AT_PS 72
#define AT_SM_QHI 0
#define AT_SM_QLO 34816
#define AT_SM_KHI 69632
#define AT_SM_KLO 87040
#define AT_SM_VHI 104448
#define AT_SM_VLO 122880
#define AT_SM_PHI 141312
#define AT_SM_PLO 159744
#define AT_SMEM   178176

__global__ __launch_bounds__(256, 1)
void attn_mma_kernel() {
    extern __shared__ char sm[];
    const uint32_t sb = smem_u32(sm);
    const int tid  = threadIdx.x;
    const int wid  = tid >> 5;
    const int lane = tid & 31;
    const int qt = blockIdx.x;       // q tile 0..15 (128 rows each)
    const int bh = blockIdx.y;       // b*16+h
    const int q0 = qt * 128;
    const float scale = 0.08838834764831845f;  // 1/sqrt(128)

    const float* Qp = g_q + (size_t)bh * SEQLEN * HDIM;
    const float* Kp = g_k + (size_t)bh * SEQLEN * HDIM;
    const float* Vp = g_v + (size_t)bh * SEQLEN * HDIM;

    const int lrow = (lane & 7) + ((lane >> 3) & 1) * 8;
    const int lk   = (lane >> 4) * 8;
    const int g    = lane >> 2;
    const int t    = lane & 3;

    // ---- load Q tile once: prescale, split, [q][d] stride 136 ----
    {
        const int row = tid >> 1;
        const int cb  = (tid & 1) * 64;
        const float* qrow = Qp + (size_t)(q0 + row) * HDIM;
#pragma unroll
        for (int c = 0; c < 16; c++) {
            const int col = cb + c * 4;
            float4 v = *(const float4*)(qrow + col);
            v.x *= scale; v.y *= scale; v.z *= scale; v.w *= scale;
            __nv_bfloat16 hx, lx, hy, ly;
            split_bf16(v.x, hx, lx); split_bf16(v.y, hy, ly);
            *(__nv_bfloat162*)(sm + AT_SM_QHI + (row * AT_QS + col) * 2) = __nv_bfloat162(hx, hy);
            *(__nv_bfloat162*)(sm + AT_SM_QLO + (row * AT_QS + col) * 2) = __nv_bfloat162(lx, ly);
            split_bf16(v.z, hx, lx); split_bf16(v.w, hy, ly);
            *(__nv_bfloat162*)(sm + AT_SM_QHI + (row * AT_QS + col + 2) * 2) = __nv_bfloat162(hx, hy);
            *(__nv_bfloat162*)(sm + AT_SM_QLO + (row * AT_QS + col + 2) * 2) = __nv_bfloat162(lx, ly);
        }
    }

    float mi0 = -INFINITY, mi1 = -INFINITY, li0 = 0.f, li1 = 0.f;
    float o[16][4];
#pragma unroll
    for (int nf = 0; nf < 16; nf++)
#pragma unroll
        for (int c = 0; c < 4; c++) o[nf][c] = 0.f;

    const int qrow0 = q0 + wid * 16 + g;
    const int qrow1 = qrow0 + 8;
    const int jmax  = 2 * qt + 2;

    const uint32_t aQh = sb + AT_SM_QHI + (uint32_t)(((wid * 16 + lrow) * AT_QS + lk) * 2);
    const uint32_t aQl = aQh + (AT_SM_QLO - AT_SM_QHI);
    const uint32_t bKh = sb + AT_SM_KHI + (uint32_t)((lrow * AT_QS + lk) * 2);
    const uint32_t bKl = bKh + (AT_SM_KLO - AT_SM_KHI);
    const uint32_t aPh = sb + AT_SM_PHI + (uint32_t)(((wid * 16 + lrow) * AT_PS + lk) * 2);
    const uint32_t aPl = aPh + (AT_SM_PLO - AT_SM_PHI);
    const uint32_t bVh = sb + AT_SM_VHI + (uint32_t)((lrow * AT_PS + lk) * 2);
    const uint32_t bVl = bVh + (AT_SM_VLO - AT_SM_VHI);

    for (int j = 0; j < jmax; j++) {
        const int k0 = j * 64;
        __syncthreads();   // protect K/V/P overwrite vs previous iteration reads

        // ---- load K (row-major, split) and V (transposed, split) ----
        {
            const int row = tid >> 2;            // 0..63
            const int cb  = (tid & 3) * 32;
            const float* krow = Kp + (size_t)(k0 + row) * HDIM;
            const float* vrow = Vp + (size_t)(k0 + row) * HDIM;
#pragma unroll
            for (int c = 0; c < 8; c++) {
                const int col = cb + c * 4;
                float4 kv4 = *(const float4*)(krow + col);
                __nv_bfloat16 hx, lx, hy, ly;
                split_bf16(kv4.x, hx, lx); split_bf16(kv4.y, hy, ly);
                *(__nv_bfloat162*)(sm + AT_SM_KHI + (row * AT_QS + col) * 2) = __nv_bfloat162(hx, hy);
                *(__nv_bfloat162*)(sm + AT_SM_KLO + (row * AT_QS + col) * 2) = __nv_bfloat162(lx, ly);
                split_bf16(kv4.z, hx, lx); split_bf16(kv4.w, hy, ly);
                *(__nv_bfloat162*)(sm + AT_SM_KHI + (row * AT_QS + col + 2) * 2) = __nv_bfloat162(hx, hy);
                *(__nv_bfloat162*)(sm + AT_SM_KLO + (row * AT_QS + col + 2) * 2) = __nv_bfloat162(lx, ly);

                float4 vv4 = *(const float4*)(vrow + col);
                float ve[4] = {vv4.x, vv4.y, vv4.z, vv4.w};
#pragma unroll
                for (int e = 0; e < 4; e++) {
                    __nv_bfloat16 vh, vl;
                    split_bf16(ve[e], vh, vl);
                    *(__nv_bfloat16*)(sm + AT_SM_VHI + ((col + e) * AT_PS + row) * 2) = vh;
                    *(__nv_bfloat16*)(sm + AT_SM_VLO + ((col + e) * AT_PS + row) * 2) = vl;
                }
            }
        }
        __syncthreads();

        // ---- S = Q @ K^T (M=16/warp, N=64, K=128), 3-term split ----
        float s[8][4];
#pragma unroll
        for (int nf = 0; nf < 8; nf++)
#pragma unroll
            for (int c = 0; c < 4; c++) s[nf][c] = 0.f;

#pragma unroll
        for (int ks = 0; ks < 8; ks++) {
            const uint32_t ko = (uint32_t)(ks * 32);
            uint32_t qh0, qh1, qh2, qh3, ql0, ql1, ql2, ql3;
            LDSM_X4(qh0, qh1, qh2, qh3, aQh + ko);
            LDSM_X4(ql0, ql1, ql2, ql3, aQl + ko);
#pragma unroll
            for (int p = 0; p < 4; p++) {
                const uint32_t po = (uint32_t)(p * 16 * AT_QS * 2) + ko;
                uint32_t kh0, kh1, kh2, kh3, kl0, kl1, kl2, kl3;
                LDSM_X4(kh0, kh1, kh2, kh3, bKh + po);
                LDSM_X4(kl0, kl1, kl2, kl3, bKl + po);
                MMA_BF16(s[2*p][0], s[2*p][1], s[2*p][2], s[2*p][3],
                         qh0, qh1, qh2, qh3, kh0, kh2);
                MMA_BF16(s[2*p][0], s[2*p][1], s[2*p][2], s[2*p][3],
                         qh0, qh1, qh2, qh3, kl0, kl2);
                MMA_BF16(s[2*p][0], s[2*p][1], s[2*p][2], s[2*p][3],
                         ql0, ql1, ql2, ql3, kh0, kh2);
                MMA_BF16(s[2*p+1][0], s[2*p+1][1], s[2*p+1][2], s[2*p+1][3],
                         qh0, qh1, qh2, qh3, kh1, kh3);
                MMA_BF16(s[2*p+1][0], s[2*p+1][1], s[2*p+1][2], s[2*p+1][3],
                         qh0, qh1, qh2, qh3, kl1, kl3);
                MMA_BF16(s[2*p+1][0], s[2*p+1][1], s[2*p+1][2], s[2*p+1][3],
                         ql0, ql1, ql2, ql3, kh1, kh3);
            }
        }

        // ---- causal mask (only last two tiles overlap diagonal) ----
        if (j >= 2 * qt) {
#pragma unroll
            for (int nf = 0; nf < 8; nf++) {
                const int kc = k0 + nf * 8 + t * 2;
                if (kc     > qrow0) s[nf][0] = -INFINITY;
                if (kc + 1 > qrow0) s[nf][1] = -INFINITY;
                if (kc     > qrow1) s[nf][2] = -INFINITY;
                if (kc + 1 > qrow1) s[nf][3] = -INFINITY;
            }
        }

        // ---- online softmax (rows fully within 4 lanes) ----
        float rmax0 = -INFINITY, rmax1 = -INFINITY;
#pragma unroll
        for (int nf = 0; nf < 8; nf++) {
            rmax0 = fmaxf(rmax0, fmaxf(s[nf][0], s[nf][1]));
            rmax1 = fmaxf(rmax1, fmaxf(s[nf][2], s[nf][3]));
        }
        rmax0 = fmaxf(rmax0, __shfl_xor_sync(0xffffffffu, rmax0, 1));
        rmax0 = fmaxf(rmax0, __shfl_xor_sync(0xffffffffu, rmax0, 2));
        rmax1 = fmaxf(rmax1, __shfl_xor_sync(0xffffffffu, rmax1, 1));
        rmax1 = fmaxf(rmax1, __shfl_xor_sync(0xffffffffu, rmax1, 2));
        const float mn0 = fmaxf(mi0, rmax0);
        const float mn1 = fmaxf(mi1, rmax1);
        const float corr0 = __expf(mi0 - mn0);
        const float corr1 = __expf(mi1 - mn1);
        mi0 = mn0; mi1 = mn1;

        float rs0 = 0.f, rs1 = 0.f;
        const int prow0 = wid * 16 + g;
#pragma unroll
        for (int nf = 0; nf < 8; nf++) {
            const float p0 = __expf(s[nf][0] - mn0);
            const float p1 = __expf(s[nf][1] - mn0);
            const float p2 = __expf(s[nf][2] - mn1);
            const float p3 = __expf(s[nf][3] - mn1);
            rs0 += p0 + p1;
            rs1 += p2 + p3;
            const int col = nf * 8 + t * 2;
            __nv_bfloat16 h0, l0, h1, l1;
            split_bf16(p0, h0, l0); split_bf16(p1, h1, l1);
            *(__nv_bfloat162*)(sm + AT_SM_PHI + (prow0 * AT_PS + col) * 2) = __nv_bfloat162(h0, h1);
            *(__nv_bfloat162*)(sm + AT_SM_PLO + (prow0 * AT_PS + col) * 2) = __nv_bfloat162(l0, l1);
            split_bf16(p2, h0, l0); split_bf16(p3, h1, l1);
            *(__nv_bfloat162*)(sm + AT_SM_PHI + ((prow0 + 8) * AT_PS + col) * 2) = __nv_bfloat162(h0, h1);
            *(__nv_bfloat162*)(sm + AT_SM_PLO + ((prow0 + 8) * AT_PS + col) * 2) = __nv_bfloat162(l0, l1);
        }
        rs0 += __shfl_xor_sync(0xffffffffu, rs0, 1);
        rs0 += __shfl_xor_sync(0xffffffffu, rs0, 2);
        rs1 += __shfl_xor_sync(0xffffffffu, rs1, 1);
        rs1 += __shfl_xor_sync(0xffffffffu, rs1, 2);
        li0 = li0 * corr0 + rs0;
        li1 = li1 * corr1 + rs1;

#pragma unroll
        for (int nf = 0; nf < 16; nf++) {
            o[nf][0] *= corr0; o[nf][1] *= corr0;
            o[nf][2] *= corr1; o[nf][3] *= corr1;
        }
        __syncthreads();   // P visible before PV reads

        // ---- O += P @ V (M=16/warp, N=128, K=64), 3-term split ----
#pragma unroll
        for (int ks = 0; ks < 4; ks++) {
            const uint32_t ko = (uint32_t)(ks * 32);
            uint32_t ph0, ph1, ph2, ph3, pl0, pl1, pl2, pl3;
            LDSM_X4(ph0, ph1, ph2, ph3, aPh + ko);
            LDSM_X4(pl0, pl1, pl2, pl3, aPl + ko);
#pragma unroll
            for (int p = 0; p < 8; p++) {
                const uint32_t po = (uint32_t)(p * 16 * AT_PS * 2) + ko;
                uint32_t vh0, vh1, vh2, vh3, vl0, vl1, vl2, vl3;
                LDSM_X4(vh0, vh1, vh2, vh3, bVh + po);
                LDSM_X4(vl0, vl1, vl2, vl3, bVl + po);
                MMA_BF16(o[2*p][0], o[2*p][1], o[2*p][2], o[2*p][3],
                         ph0, ph1, ph2, ph3, vh0, vh2);
                MMA_BF16(o[2*p][0], o[2*p][1], o[2*p][2], o[2*p][3],
                         ph0, ph1, ph2, ph3, vl0, vl2);
                MMA_BF16(o[2*p][0], o[2*p][1], o[2*p][2], o[2*p][3],
                         pl0, pl1, pl2, pl3, vh0, vh2);
                MMA_BF16(o[2*p+1][0], o[2*p+1][1], o[2*p+1][2], o[2*p+1][3],
                         ph0, ph1, ph2, ph3, vh1, vh3);
                MMA_BF16(o[2*p+1][0], o[2*p+1][1], o[2*p+1][2], o[2*p+1][3],
                         ph0, ph1, ph2, ph3, vl1, vl3);
                MMA_BF16(o[2*p+1][0], o[2*p+1][1], o[2*p+1][2], o[2*p+1][3],
                         pl0, pl1, pl2, pl3, vh1, vh3);
            }
        }
    }

    // ---- normalize + write [b, s, h*128+d] ----
    const int b = bh >> 4, h = bh & 15;
    const float inv0 = 1.0f / li0;
    const float inv1 = 1.0f / li1;
    const size_t r0base = ((size_t)b * SEQLEN + qrow0) * HID + h * HDIM;
    const size_t r1base = ((size_t)b * SEQLEN + qrow1) * HID + h * HDIM;
#pragma unroll
    for (int nf = 0; nf < 16; nf++) {
        const int d = nf * 8 + t * 2;
        float2 v0, v1;
        v0.x = o[nf][0] * inv0; v0.y = o[nf][1] * inv0;
        v1.x = o[nf][2] * inv1; v1.y = o[nf][3] * inv1;
        *(float2*)(g_attn + r0base + d) = v0;
        *(float2*)(g_attn + r1base + d) = v1;
    }
}

// ---------------------------------------------------------------------------
extern "C" void kernel_launch(void* const* d_in, const int* in_sizes, int n_in,
                              void* d_out, int out_size) {
    const float* x  = (const float*)d_in[0];
    const float* wq = (const float*)d_in[1];
    const float* wk = (const float*)d_in[2];
    const float* wv = (const float*)d_in[3];
    const float* wo = (const float*)d_in[4];
    const float* bq = (const float*)d_in[5];
    const float* bk = (const float*)d_in[6];
    const float* bv = (const float*)d_in[7];
    const float* bo = (const float*)d_in[8];
    float* out = (float*)d_out;

    cudaFuncSetAttribute(gemm_qkv_kernel,
                         cudaFuncAttributeMaxDynamicSharedMemorySize, GSM_TOTAL);
    cudaFuncSetAttribute(gemm_out_kernel,
                         cudaFuncAttributeMaxDynamicSharedMemorySize, GSM_TOTAL);
    cudaFuncSetAttribute(attn_mma_kernel,
                         cudaFuncAttributeMaxDynamicSharedMemorySize, AT_SMEM);

    // 1) QKV projections on mma.sync bf16 (3-term split)
    gemm_qkv_kernel<<<dim3(HID / 128, MTOT / 128, 3), 256, GSM_TOTAL>>>(
        x, wq, wk, wv, bq, bk, bv);
    // 2) Causal flash attention on mma.sync bf16 (3-term split)
    attn_mma_kernel<<<dim3(SEQLEN / 128, BATCHSZ * NHEADS), 256, AT_SMEM>>>();
    // 3) Output projection on mma.sync bf16
    gemm_out_kernel<<<dim3(HID / 128, MTOT / 128), 256, GSM_TOTAL>>>(wo, bo, out);
}

// round 6
// speedup vs baseline: 2.6709x; 1.1606x over previous
#include <cuda_runtime.h>
#include <cuda_bf16.h>
#include <math.h>
#include <cstdint>
#include <string.h>

#define HID     2048
#define NHEADS  16
#define HDIM    128
#define BATCHSZ 2
#define SEQLEN  2048
#define MTOT    (BATCHSZ * SEQLEN)   // 4096

// ---------------- scratch (allocation-free), all bf16 split pairs ----------
__device__ __nv_bfloat16 g_xhi[MTOT * HID],  g_xlo[MTOT * HID];
__device__ __nv_bfloat16 g_whi[4 * HID * HID], g_wlo[4 * HID * HID];
__device__ __nv_bfloat16 g_qhi[MTOT * HID],  g_qlo[MTOT * HID];
__device__ __nv_bfloat16 g_khi[MTOT * HID],  g_klo[MTOT * HID];
__device__ __nv_bfloat16 g_vhi[MTOT * HID],  g_vlo[MTOT * HID];
__device__ __nv_bfloat16 g_ohi[MTOT * HID],  g_olo[MTOT * HID];

// ============================ helpers ======================================
__device__ __forceinline__ uint32_t smem_u32(const void* p) {
    uint32_t a;
    asm("{ .reg .u64 t; cvta.to.shared.u64 t, %1; cvt.u32.u64 %0, t; }"
        : "=r"(a) : "l"(p));
    return a;
}

#define LDSM_X4(r0, r1, r2, r3, addr)                                    \
    asm volatile("ldmatrix.sync.aligned.m8n8.x4.shared.b16 "             \
                 "{%0,%1,%2,%3}, [%4];"                                  \
                 : "=r"(r0), "=r"(r1), "=r"(r2), "=r"(r3) : "r"(addr))

#define LDSM_X4_T(r0, r1, r2, r3, addr)                                  \
    asm volatile("ldmatrix.sync.aligned.m8n8.x4.trans.shared.b16 "       \
                 "{%0,%1,%2,%3}, [%4];"                                  \
                 : "=r"(r0), "=r"(r1), "=r"(r2), "=r"(r3) : "r"(addr))

#define MMA_BF16(c0, c1, c2, c3, a0, a1, a2, a3, b0, b1)                 \
    asm volatile("mma.sync.aligned.m16n8k16.row.col.f32.bf16.bf16.f32 "  \
                 "{%0,%1,%2,%3}, {%4,%5,%6,%7}, {%8,%9}, {%0,%1,%2,%3};" \
                 : "+f"(c0), "+f"(c1), "+f"(c2), "+f"(c3)                \
                 : "r"(a0), "r"(a1), "r"(a2), "r"(a3), "r"(b0), "r"(b1))

#define CP16(saddr, gptr)                                                \
    asm volatile("cp.async.cg.shared.global [%0], [%1], 16;"             \
                 :: "r"(saddr), "l"(gptr))
#define CP_COMMIT() asm volatile("cp.async.commit_group;" ::: "memory")
#define CP_WAIT0()  asm volatile("cp.async.wait_group 0;" ::: "memory")

__device__ __forceinline__ void split_bf16(float x, __nv_bfloat16& hi, __nv_bfloat16& lo) {
    hi = __float2bfloat16_rn(x);
    lo = __float2bfloat16_rn(x - __bfloat162float(hi));
}
__device__ __forceinline__ uint32_t packbf(__nv_bfloat16 a, __nv_bfloat16 b) {
    __nv_bfloat162 t; t.x = a; t.y = b;
    uint32_t u; memcpy(&u, &t, 4);
    return u;
}

// ======================= split kernels (one-time) ==========================
__global__ __launch_bounds__(256)
void split_f32_kernel(const float* __restrict__ src,
                      __nv_bfloat16* __restrict__ hi,
                      __nv_bfloat16* __restrict__ lo, int n) {
    const int i = (blockIdx.x * 256 + threadIdx.x) * 4;
    if (i >= n) return;
    float4 v = *(const float4*)(src + i);
    __nv_bfloat16 hx, lx, hy, ly;
    split_bf16(v.x, hx, lx); split_bf16(v.y, hy, ly);
    *(__nv_bfloat162*)(hi + i) = __nv_bfloat162(hx, hy);
    *(__nv_bfloat162*)(lo + i) = __nv_bfloat162(lx, ly);
    split_bf16(v.z, hx, lx); split_bf16(v.w, hy, ly);
    *(__nv_bfloat162*)(hi + i + 2) = __nv_bfloat162(hx, hy);
    *(__nv_bfloat162*)(lo + i + 2) = __nv_bfloat162(lx, ly);
}

// ================= pipelined bf16-split GEMM (cp.async) ====================
// C[M=4096, N=2048] = A @ W^T + bias, pre-split bf16 inputs.
// CTA 128x128, 8 warps (2M x 4N), warp 64x32. K chunk 32. 2-stage cp.async.
#define KSTRIDE 40
#define TILE_B  (128 * KSTRIDE * 2)      // 10240 B
#define STAGE_B (4 * TILE_B)             // 40960 B
#define GSM_TOTAL (2 * STAGE_B)          // 81920 B
#define NKC (HID / 32)                   // 64

// MODE 0: fp32 Out[m*HID+n].  MODE 1: bf16 split OutHi/OutLo [b,h,s,d] * scale
template <int MODE>
__device__ __forceinline__ void gemm_body(const __nv_bfloat16* __restrict__ Ahi,
                                          const __nv_bfloat16* __restrict__ Alo,
                                          const __nv_bfloat16* __restrict__ Whi,
                                          const __nv_bfloat16* __restrict__ Wlo,
                                          const float* __restrict__ Bias,
                                          float* __restrict__ OutF,
                                          __nv_bfloat16* __restrict__ OutHi,
                                          __nv_bfloat16* __restrict__ OutLo,
                                          float scale) {
    extern __shared__ char sm[];
    const uint32_t sb = smem_u32(sm);
    const int tid  = threadIdx.x;
    const int wid  = tid >> 5;
    const int lane = tid & 31;
    const int m0 = blockIdx.y * 128;
    const int n0 = blockIdx.x * 128;
    const int wm = wid & 1;
    const int wn = wid >> 1;

    const int lrow = (lane & 7) + ((lane >> 3) & 1) * 8;
    const int lk   = (lane >> 4) * 8;

    // loader: chunk = 16B of one row; per tile thread handles chunks tid, tid+256
    const int r0 = tid >> 2;                 // rows 0..63
    const int c0 = (tid & 3) * 8;            // bf16 col offset 0,8,16,24
    const __nv_bfloat16* gA[4];
    gA[0] = Ahi + (size_t)(m0 + r0) * HID + c0;
    gA[1] = Alo + (size_t)(m0 + r0) * HID + c0;
    gA[2] = Whi + (size_t)(n0 + r0) * HID + c0;
    gA[3] = Wlo + (size_t)(n0 + r0) * HID + c0;
    const uint32_t sA0 = sb + (uint32_t)(r0 * 80 + (tid & 3) * 16);
    // second half: rows +64
    const uint32_t sA1 = sA0 + 64 * 80;

    float acc[4][4][4];
#pragma unroll
    for (int i = 0; i < 4; i++)
#pragma unroll
        for (int j = 0; j < 4; j++)
#pragma unroll
            for (int c = 0; c < 4; c++) acc[i][j][c] = 0.f;

    // ---- prologue: stage 0 ----
#pragma unroll
    for (int t = 0; t < 4; t++) {
        CP16(sA0 + t * TILE_B, gA[t]);
        CP16(sA1 + t * TILE_B, gA[t] + (size_t)64 * HID);
    }
    CP_COMMIT();

    for (int kc = 0; kc < NKC; kc++) {
        CP_WAIT0();
        __syncthreads();
        if (kc + 1 < NKC) {
            const uint32_t soff = ((kc + 1) & 1) * STAGE_B;
            const int go = (kc + 1) * 32;
#pragma unroll
            for (int t = 0; t < 4; t++) {
                CP16(sA0 + soff + t * TILE_B, gA[t] + go);
                CP16(sA1 + soff + t * TILE_B, gA[t] + (size_t)64 * HID + go);
            }
            CP_COMMIT();
        }

        const uint32_t stg = (kc & 1) * STAGE_B;
        const uint32_t aH = sb + stg + (uint32_t)(((wm * 64 + lrow) * KSTRIDE + lk) * 2);
        const uint32_t bH = sb + stg + 2 * TILE_B +
                            (uint32_t)(((wn * 32 + lrow) * KSTRIDE + lk) * 2);
#pragma unroll
        for (int ks = 0; ks < 2; ks++) {
            const uint32_t ko = (uint32_t)(ks * 32);
            uint32_t bh[4][2], bl[4][2];
#pragma unroll
            for (int p = 0; p < 2; p++) {
                const uint32_t ba = bH + (uint32_t)(p * 16 * KSTRIDE * 2) + ko;
                uint32_t q0, q1, q2, q3;
                LDSM_X4(q0, q1, q2, q3, ba);
                bh[2 * p][0] = q0; bh[2 * p][1] = q2;
                bh[2 * p + 1][0] = q1; bh[2 * p + 1][1] = q3;
                LDSM_X4(q0, q1, q2, q3, ba + TILE_B);
                bl[2 * p][0] = q0; bl[2 * p][1] = q2;
                bl[2 * p + 1][0] = q1; bl[2 * p + 1][1] = q3;
            }
#pragma unroll
            for (int mf = 0; mf < 4; mf++) {
                const uint32_t aa = aH + (uint32_t)(mf * 16 * KSTRIDE * 2) + ko;
                uint32_t ah0, ah1, ah2, ah3, al0, al1, al2, al3;
                LDSM_X4(ah0, ah1, ah2, ah3, aa);
                LDSM_X4(al0, al1, al2, al3, aa + TILE_B);
#pragma unroll
                for (int nf = 0; nf < 4; nf++) {
                    MMA_BF16(acc[mf][nf][0], acc[mf][nf][1], acc[mf][nf][2], acc[mf][nf][3],
                             ah0, ah1, ah2, ah3, bh[nf][0], bh[nf][1]);
                    MMA_BF16(acc[mf][nf][0], acc[mf][nf][1], acc[mf][nf][2], acc[mf][nf][3],
                             ah0, ah1, ah2, ah3, bl[nf][0], bl[nf][1]);
                    MMA_BF16(acc[mf][nf][0], acc[mf][nf][1], acc[mf][nf][2], acc[mf][nf][3],
                             al0, al1, al2, al3, bh[nf][0], bh[nf][1]);
                }
            }
        }
    }

    // ---- epilogue ----
    const int g = lane >> 2;
    const int t = lane & 3;
#pragma unroll
    for (int mf = 0; mf < 4; mf++) {
#pragma unroll
        for (int nf = 0; nf < 4; nf++) {
            const int m_lo = m0 + wm * 64 + mf * 16 + g;
            const int n    = n0 + wn * 32 + nf * 8 + t * 2;
            const float2 bb = *(const float2*)(Bias + n);
            float2 v0, v1;
            v0.x = acc[mf][nf][0] + bb.x; v0.y = acc[mf][nf][1] + bb.y;
            v1.x = acc[mf][nf][2] + bb.x; v1.y = acc[mf][nf][3] + bb.y;
            if (MODE == 0) {
                *(float2*)(OutF + (size_t)m_lo * HID + n)       = v0;
                *(float2*)(OutF + (size_t)(m_lo + 8) * HID + n) = v1;
            } else {
                v0.x *= scale; v0.y *= scale; v1.x *= scale; v1.y *= scale;
                const int h = n >> 7;
                const int d = n & (HDIM - 1);
                const int b0b = m_lo >> 11, s0 = m_lo & (SEQLEN - 1);
                const int b1b = (m_lo + 8) >> 11, s1 = (m_lo + 8) & (SEQLEN - 1);
                const size_t o0 = ((size_t)(b0b * NHEADS + h) * SEQLEN + s0) * HDIM + d;
                const size_t o1 = ((size_t)(b1b * NHEADS + h) * SEQLEN + s1) * HDIM + d;
                __nv_bfloat16 hx, lx, hy, ly;
                split_bf16(v0.x, hx, lx); split_bf16(v0.y, hy, ly);
                *(__nv_bfloat162*)(OutHi + o0) = __nv_bfloat162(hx, hy);
                *(__nv_bfloat162*)(OutLo + o0) = __nv_bfloat162(lx, ly);
                split_bf16(v1.x, hx, lx); split_bf16(v1.y, hy, ly);
                *(__nv_bfloat162*)(OutHi + o1) = __nv_bfloat162(hx, hy);
                *(__nv_bfloat162*)(OutLo + o1) = __nv_bfloat162(lx, ly);
            }
        }
    }
}

__global__ __launch_bounds__(256, 2)
void gemm_qkv_kernel(const float* __restrict__ bq, const float* __restrict__ bk,
                     const float* __restrict__ bv) {
    const int z = blockIdx.z;
    const __nv_bfloat16* Whi = g_whi + (size_t)z * HID * HID;
    const __nv_bfloat16* Wlo = g_wlo + (size_t)z * HID * HID;
    const float* B = (z == 0) ? bq : (z == 1 ? bk : bv);
    __nv_bfloat16* Ohi = (z == 0) ? g_qhi : (z == 1 ? g_khi : g_vhi);
    __nv_bfloat16* Olo = (z == 0) ? g_qlo : (z == 1 ? g_klo : g_vlo);
    const float scale = (z == 0) ? 0.08838834764831845f : 1.0f;
    gemm_body<1>(g_xhi, g_xlo, Whi, Wlo, B, nullptr, Ohi, Olo, scale);
}

__global__ __launch_bounds__(256, 2)
void gemm_out_kernel(const float* __restrict__ bo, float* __restrict__ out) {
    gemm_body<0>(g_ohi, g_olo, g_whi + (size_t)3 * HID * HID,
                 g_wlo + (size_t)3 * HID * HID, bo, out, nullptr, nullptr, 1.0f);
}

// ===================== Flash attention (bf16 mma, P in regs) ===============
// CTA = 128 q-rows of one (b,h). kv tile 64. Pre-split Q/K/V from gmem (pure
// copies). P kept in registers (QK C-frag == PV A-frag). V via ldmatrix.trans.
#define AQ 136
#define AT_QHI 0
#define AT_QLO 34816
#define AT_KHI 69632
#define AT_KLO 87040
#define AT_VHI 104448
#define AT_VLO 121856
#define AT_SMEM 139264

__global__ __launch_bounds__(256, 1)
void attn_mma_kernel() {
    extern __shared__ char sm[];
    const uint32_t sb = smem_u32(sm);
    const int tid  = threadIdx.x;
    const int wid  = tid >> 5;
    const int lane = tid & 31;
    const int qt = blockIdx.x;
    const int bh = blockIdx.y;
    const int q0 = qt * 128;

    const size_t base = (size_t)bh * SEQLEN * HDIM;

    const int lrow = (lane & 7) + ((lane >> 3) & 1) * 8;
    const int lk   = (lane >> 4) * 8;
    const int g    = lane >> 2;
    const int t    = lane & 3;

    // ---- load Q tile (pure copy of pre-scaled, pre-split bf16) ----
    {
        const int row  = tid >> 1;
        const int half = (tid & 1) * 64;
        const __nv_bfloat16* qh = g_qhi + base + (size_t)(q0 + row) * HDIM + half;
        const __nv_bfloat16* ql = g_qlo + base + (size_t)(q0 + row) * HDIM + half;
        char* dh = sm + AT_QHI + (row * AQ + half) * 2;
        char* dl = sm + AT_QLO + (row * AQ + half) * 2;
#pragma unroll
        for (int c = 0; c < 8; c++) {
            *(uint4*)(dh + c * 16) = *(const uint4*)(qh + c * 8);
            *(uint4*)(dl + c * 16) = *(const uint4*)(ql + c * 8);
        }
    }

    float mi0 = -INFINITY, mi1 = -INFINITY, li0 = 0.f, li1 = 0.f;
    float o[16][4];
#pragma unroll
    for (int nf = 0; nf < 16; nf++)
#pragma unroll
        for (int c = 0; c < 4; c++) o[nf][c] = 0.f;

    const int qrow0 = q0 + wid * 16 + g;
    const int qrow1 = qrow0 + 8;
    const int jmax  = 2 * qt + 2;

    const uint32_t aQh = sb + AT_QHI + (uint32_t)(((wid * 16 + lrow) * AQ + lk) * 2);
    const uint32_t aQl = aQh + (AT_QLO - AT_QHI);
    const uint32_t bKh = sb + AT_KHI + (uint32_t)((lrow * AQ + lk) * 2);
    const uint32_t bKl = bKh + (AT_KLO - AT_KHI);
    // V trans-ldmatrix lane base: row = kv-within-16, col = d-offset 0/8
    const uint32_t bVt = sb + AT_VHI +
        (uint32_t)((((lane & 7) + ((lane >> 3) & 1) * 8) * AQ + ((lane >> 4) & 1) * 8) * 2);

    for (int j = 0; j < jmax; j++) {
        const int k0 = j * 64;
        __syncthreads();   // previous PV reads of K/V done

        // ---- load K/V tiles (pure copies) ----
        {
            const int row = tid >> 2;
            const int qtr = (tid & 3) * 32;
            const size_t gsrc = base + (size_t)(k0 + row) * HDIM + qtr;
            const int doff = (row * AQ + qtr) * 2;
#pragma unroll
            for (int c = 0; c < 4; c++) {
                *(uint4*)(sm + AT_KHI + doff + c * 16) = *(const uint4*)(g_khi + gsrc + c * 8);
                *(uint4*)(sm + AT_KLO + doff + c * 16) = *(const uint4*)(g_klo + gsrc + c * 8);
                *(uint4*)(sm + AT_VHI + doff + c * 16) = *(const uint4*)(g_vhi + gsrc + c * 8);
                *(uint4*)(sm + AT_VLO + doff + c * 16) = *(const uint4*)(g_vlo + gsrc + c * 8);
            }
        }
        __syncthreads();

        // ---- S = Q @ K^T ----
        float s[8][4];
#pragma unroll
        for (int nf = 0; nf < 8; nf++)
#pragma unroll
            for (int c = 0; c < 4; c++) s[nf][c] = 0.f;

#pragma unroll
        for (int ks = 0; ks < 8; ks++) {
            const uint32_t ko = (uint32_t)(ks * 32);
            uint32_t qh0, qh1, qh2, qh3, ql0, ql1, ql2, ql3;
            LDSM_X4(qh0, qh1, qh2, qh3, aQh + ko);
            LDSM_X4(ql0, ql1, ql2, ql3, aQl + ko);
#pragma unroll
            for (int p = 0; p < 4; p++) {
                const uint32_t po = (uint32_t)(p * 16 * AQ * 2) + ko;
                uint32_t kh0, kh1, kh2, kh3, kl0, kl1, kl2, kl3;
                LDSM_X4(kh0, kh1, kh2, kh3, bKh + po);
                LDSM_X4(kl0, kl1, kl2, kl3, bKl + po);
                MMA_BF16(s[2*p][0], s[2*p][1], s[2*p][2], s[2*p][3],
                         qh0, qh1, qh2, qh3, kh0, kh2);
                MMA_BF16(s[2*p][0], s[2*p][1], s[2*p][2], s[2*p][3],
                         qh0, qh1, qh2, qh3, kl0, kl2);
                MMA_BF16(s[2*p][0], s[2*p][1], s[2*p][2], s[2*p][3],
                         ql0, ql1, ql2, ql3, kh0, kh2);
                MMA_BF16(s[2*p+1][0], s[2*p+1][1], s[2*p+1][2], s[2*p+1][3],
                         qh0, qh1, qh2, qh3, kh1, kh3);
                MMA_BF16(s[2*p+1][0], s[2*p+1][1], s[2*p+1][2], s[2*p+1][3],
                         qh0, qh1, qh2, qh3, kl1, kl3);
                MMA_BF16(s[2*p+1][0], s[2*p+1][1], s[2*p+1][2], s[2*p+1][3],
                         ql0, ql1, ql2, ql3, kh1, kh3);
            }
        }

        // ---- causal mask ----
        if (j >= 2 * qt) {
#pragma unroll
            for (int nf = 0; nf < 8; nf++) {
                const int kc = k0 + nf * 8 + t * 2;
                if (kc     > qrow0) s[nf][0] = -INFINITY;
                if (kc + 1 > qrow0) s[nf][1] = -INFINITY;
                if (kc     > qrow1) s[nf][2] = -INFINITY;
                if (kc + 1 > qrow1) s[nf][3] = -INFINITY;
            }
        }

        // ---- online softmax (warp-local) + pack P into PV A-fragments ----
        float rmax0 = -INFINITY, rmax1 = -INFINITY;
#pragma unroll
        for (int nf = 0; nf < 8; nf++) {
            rmax0 = fmaxf(rmax0, fmaxf(s[nf][0], s[nf][1]));
            rmax1 = fmaxf(rmax1, fmaxf(s[nf][2], s[nf][3]));
        }
        rmax0 = fmaxf(rmax0, __shfl_xor_sync(0xffffffffu, rmax0, 1));
        rmax0 = fmaxf(rmax0, __shfl_xor_sync(0xffffffffu, rmax0, 2));
        rmax1 = fmaxf(rmax1, __shfl_xor_sync(0xffffffffu, rmax1, 1));
        rmax1 = fmaxf(rmax1, __shfl_xor_sync(0xffffffffu, rmax1, 2));
        const float mn0 = fmaxf(mi0, rmax0);
        const float mn1 = fmaxf(mi1, rmax1);
        const float corr0 = __expf(mi0 - mn0);
        const float corr1 = __expf(mi1 - mn1);
        mi0 = mn0; mi1 = mn1;

        uint32_t ph[4][4], pl[4][4];
        float rs0 = 0.f, rs1 = 0.f;
#pragma unroll
        for (int nf = 0; nf < 8; nf++) {
            const float p0 = __expf(s[nf][0] - mn0);
            const float p1 = __expf(s[nf][1] - mn0);
            const float p2 = __expf(s[nf][2] - mn1);
            const float p3 = __expf(s[nf][3] - mn1);
            rs0 += p0 + p1;
            rs1 += p2 + p3;
            __nv_bfloat16 h0, l0, h1, l1, h2, l2, h3, l3;
            split_bf16(p0, h0, l0); split_bf16(p1, h1, l1);
            split_bf16(p2, h2, l2); split_bf16(p3, h3, l3);
            const int ks = nf >> 1;
            const int r  = (nf & 1) * 2;     // a0,a1 for even nf; a2,a3 for odd
            ph[ks][r]     = packbf(h0, h1);
            ph[ks][r + 1] = packbf(h2, h3);
            pl[ks][r]     = packbf(l0, l1);
            pl[ks][r + 1] = packbf(l2, l3);
        }
        rs0 += __shfl_xor_sync(0xffffffffu, rs0, 1);
        rs0 += __shfl_xor_sync(0xffffffffu, rs0, 2);
        rs1 += __shfl_xor_sync(0xffffffffu, rs1, 1);
        rs1 += __shfl_xor_sync(0xffffffffu, rs1, 2);
        li0 = li0 * corr0 + rs0;
        li1 = li1 * corr1 + rs1;

#pragma unroll
        for (int nf = 0; nf < 16; nf++) {
            o[nf][0] *= corr0; o[nf][1] *= corr0;
            o[nf][2] *= corr1; o[nf][3] *= corr1;
        }

        // ---- O += P @ V (V via ldmatrix.trans, 3-term split) ----
#pragma unroll
        for (int ks = 0; ks < 4; ks++) {
            const uint32_t kvo = (uint32_t)(ks * 16 * AQ * 2);
#pragma unroll
            for (int p = 0; p < 8; p++) {
                const uint32_t va = bVt + kvo + (uint32_t)(p * 16 * 2);
                uint32_t vh0, vh1, vh2, vh3, vl0, vl1, vl2, vl3;
                LDSM_X4_T(vh0, vh1, vh2, vh3, va);
                LDSM_X4_T(vl0, vl1, vl2, vl3, va + (AT_VLO - AT_VHI));
                MMA_BF16(o[2*p][0], o[2*p][1], o[2*p][2], o[2*p][3],
                         ph[ks][0], ph[ks][1], ph[ks][2], ph[ks][3], vh0, vh1);
                MMA_BF16(o[2*p][0], o[2*p][1], o[2*p][2], o[2*p][3],
                         ph[ks][0], ph[ks][1], ph[ks][2], ph[ks][3], vl0, vl1);
                MMA_BF16(o[2*p][0], o[2*p][1], o[2*p][2], o[2*p][3],
                         pl[ks][0], pl[ks][1], pl[ks][2], pl[ks][3], vh0, vh1);
                MMA_BF16(o[2*p+1][0], o[2*p+1][1], o[2*p+1][2], o[2*p+1][3],
                         ph[ks][0], ph[ks][1], ph[ks][2], ph[ks][3], vh2, vh3);
                MMA_BF16(o[2*p+1][0], o[2*p+1][1], o[2*p+1][2], o[2*p+1][3],
                         ph[ks][0], ph[ks][1], ph[ks][2], ph[ks][3], vl2, vl3);
                MMA_BF16(o[2*p+1][0], o[2*p+1][1], o[2*p+1][2], o[2*p+1][3],
                         pl[ks][0], pl[ks][1], pl[ks][2], pl[ks][3], vh2, vh3);
            }
        }
    }

    // ---- normalize, split, write bf16 hi/lo in [m][HID] ----
    const int b = bh >> 4, h = bh & 15;
    const float inv0 = 1.0f / li0;
    const float inv1 = 1.0f / li1;
    const size_t r0base = ((size_t)b * SEQLEN + qrow0) * HID + h * HDIM;
    const size_t r1base = ((size_t)b * SEQLEN + qrow1) * HID + h * HDIM;
#pragma unroll
    for (int nf = 0; nf < 16; nf++) {
        const int d = nf * 8 + t * 2;
        __nv_bfloat16 hx, lx, hy, ly;
        split_bf16(o[nf][0] * inv0, hx, lx); split_bf16(o[nf][1] * inv0, hy, ly);
        *(__nv_bfloat162*)(g_ohi + r0base + d) = __nv_bfloat162(hx, hy);
        *(__nv_bfloat162*)(g_olo + r0base + d) = __nv_bfloat162(lx, ly);
        split_bf16(o[nf][2] * inv1, hx, lx); split_bf16(o[nf][3] * inv1, hy, ly);
        *(__nv_bfloat162*)(g_ohi + r1base + d) = __nv_bfloat162(hx, hy);
        *(__nv_bfloat162*)(g_olo + r1base + d) = __nv_bfloat162(lx, ly);
    }
}

// ---------------------------------------------------------------------------
extern "C" void kernel_launch(void* const* d_in, const int* in_sizes, int n_in,
                              void* d_out, int out_size) {
    const float* x  = (const float*)d_in[0];
    const float* wq = (const float*)d_in[1];
    const float* wk = (const float*)d_in[2];
    const float* wv = (const float*)d_in[3];
    const float* wo = (const float*)d_in[4];
    const float* bq = (const float*)d_in[5];
    const float* bk = (const float*)d_in[6];
    const float* bv = (const float*)d_in[7];
    const float* bo = (const float*)d_in[8];
    float* out = (float*)d_out;

    cudaFuncSetAttribute(gemm_qkv_kernel,
                         cudaFuncAttributeMaxDynamicSharedMemorySize, GSM_TOTAL);
    cudaFuncSetAttribute(gemm_out_kernel,
                         cudaFuncAttributeMaxDynamicSharedMemorySize, GSM_TOTAL);
    cudaFuncSetAttribute(attn_mma_kernel,
                         cudaFuncAttributeMaxDynamicSharedMemorySize, AT_SMEM);

    __nv_bfloat16 *xhi, *xlo, *whi, *wlo;
    cudaGetSymbolAddress((void**)&xhi, g_xhi);
    cudaGetSymbolAddress((void**)&xlo, g_xlo);
    cudaGetSymbolAddress((void**)&whi, g_whi);
    cudaGetSymbolAddress((void**)&wlo, g_wlo);

    // 0) one-time fp32 -> bf16 hi/lo splits
    const int nx = MTOT * HID, nw = HID * HID;
    split_f32_kernel<<<nx / 1024, 256>>>(x, xhi, xlo, nx);
    split_f32_kernel<<<nw / 1024, 256>>>(wq, whi + 0 * (size_t)nw, wlo + 0 * (size_t)nw, nw);
    split_f32_kernel<<<nw / 1024, 256>>>(wk, whi + 1 * (size_t)nw, wlo + 1 * (size_t)nw, nw);
    split_f32_kernel<<<nw / 1024, 256>>>(wv, whi + 2 * (size_t)nw, wlo + 2 * (size_t)nw, nw);
    split_f32_kernel<<<nw / 1024, 256>>>(wo, whi + 3 * (size_t)nw, wlo + 3 * (size_t)nw, nw);

    // 1) QKV projections (pipelined bf16 GEMM; writes split bf16, Q prescaled)
    gemm_qkv_kernel<<<dim3(HID / 128, MTOT / 128, 3), 256, GSM_TOTAL>>>(bq, bk, bv);
    // 2) Causal flash attention (bf16 mma, P in registers)
    attn_mma_kernel<<<dim3(SEQLEN / 128, BATCHSZ * NHEADS), 256, AT_SMEM>>>();
    // 3) Output projection (fp32 out)
    gemm_out_kernel<<<dim3(HID / 128, MTOT / 128), 256, GSM_TOTAL>>>(bo, out);
}